// round 16
// baseline (speedup 1.0000x reference)
#include <cuda_runtime.h>
#include <cuda_fp16.h>
#include <stdint.h>

#define NPROT 4096
#define IN_F  512
#define HALF  256
#define F     64
#define NW    128
#define ALPHA 0.2f
#define ATTN_GRID (148 * 8)

typedef unsigned long long ull;

// ---------------- scratch (device globals; no allocation allowed) ----------
__device__ __align__(16) __half g_Wh1h[NPROT * F];
__device__ __align__(16) __half g_Wh2h[NPROT * F];
__device__ float    g_s1a[NPROT], g_s2a[NPROT];   // hop1 row/col scores
__device__ float    g_s1b[NPROT], g_s2b[NPROT];   // hop2
__device__ __align__(16) unsigned g_bits1[NPROT * NW];
__device__ float    g_hp[NPROT * 2 * F];
__device__ float    g_bnsum[2 * F], g_bnsq[2 * F];

// ---------------- packed fp32x2 helpers (sm_103a FFMA2 path) ----------------
__device__ __forceinline__ ull pack2(float lo, float hi) {
    ull r; asm("mov.b64 %0, {%1, %2};" : "=l"(r) : "f"(lo), "f"(hi)); return r;
}
__device__ __forceinline__ void unpack2(ull v, float& lo, float& hi) {
    asm("mov.b64 {%0, %1}, %2;" : "=f"(lo), "=f"(hi) : "l"(v));
}
__device__ __forceinline__ void ffma2(ull& acc, ull a, ull b) {
    asm("fma.rn.f32x2 %0, %1, %2, %0;" : "+l"(acc) : "l"(a), "l"(b));
}

// ============ kernel 1: bitpack adj (pure DRAM stream) =======================
__global__ __launch_bounds__(256) void k_pack(const float* __restrict__ adj)
{
    int i = blockIdx.x, t = threadIdx.x;
    int lane = t & 31, warp = t >> 5;
    const float* arow = adj + (size_t)i * NPROT;
#pragma unroll
    for (int w = 0; w < 16; w++) {
        unsigned m = __ballot_sync(0xffffffffu, arow[w * 256 + t] > 0.f);
        if (lane == 0) g_bits1[i * NW + w * 8 + warp] = m;
    }
}

// ============ fused GEMM: Wh = h @ blockdiag(W1,W2), + score vectors ========
__global__ __launch_bounds__(256) void k_wh(const float* __restrict__ h,
                                            const float* __restrict__ W1,
                                            const float* __restrict__ W2,
                                            const float* __restrict__ a)
{
    __shared__ float hsT[2][16][16];                 // [half][k][row]
    __shared__ __align__(16) float Ws[16][128];      // [k][col]

    int t = threadIdx.x;
    int rowBase = blockIdx.x * 16;
    int cx = t & 31, ry = t >> 5;
    int half = (cx >= 16);
    int lc = (cx & 15) * 4;
    int r0 = ry * 2;

    ull acc[2][2] = {};

    int lhalf = t >> 7, lt63 = t & 63;
    int lrow = lt63 >> 2, lk4 = (lt63 & 3) * 4;
    int wkk = t >> 4, wc8 = (t & 15) * 8;

    for (int k0 = 0; k0 < HALF; k0 += 16) {
        if ((t & 127) < 64) {
            float4 hv = *(const float4*)&h[(rowBase + lrow) * IN_F + lhalf * HALF + k0 + lk4];
            hsT[lhalf][lk4 + 0][lrow] = hv.x;
            hsT[lhalf][lk4 + 1][lrow] = hv.y;
            hsT[lhalf][lk4 + 2][lrow] = hv.z;
            hsT[lhalf][lk4 + 3][lrow] = hv.w;
        }
        const float* Wsrc = (wc8 < 64) ? &W1[(k0 + wkk) * F + wc8]
                                       : &W2[(k0 + wkk) * F + (wc8 - 64)];
        *(float4*)&Ws[wkk][wc8]     = *(const float4*)Wsrc;
        *(float4*)&Ws[wkk][wc8 + 4] = *(const float4*)(Wsrc + 4);
        __syncthreads();
#pragma unroll
        for (int kk = 0; kk < 16; kk++) {
            float a0 = hsT[half][kk][r0];
            float a1 = hsT[half][kk][r0 + 1];
            ull A0 = pack2(a0, a0), A1 = pack2(a1, a1);
            ulonglong2 bb = *(const ulonglong2*)&Ws[kk][cx * 4];
            ffma2(acc[0][0], A0, bb.x); ffma2(acc[0][1], A0, bb.y);
            ffma2(acc[1][0], A1, bb.x); ffma2(acc[1][1], A1, bb.y);
        }
        __syncthreads();
    }

    float o[2][4];
    unpack2(acc[0][0], o[0][0], o[0][1]); unpack2(acc[0][1], o[0][2], o[0][3]);
    unpack2(acc[1][0], o[1][0], o[1][1]); unpack2(acc[1][1], o[1][2], o[1][3]);

    __half* dsth = half ? g_Wh2h : g_Wh1h;
#pragma unroll
    for (int r = 0; r < 2; r++) {
        __half2* p = (__half2*)&dsth[(rowBase + r0 + r) * F + lc];
        p[0] = __floats2half2_rn(o[r][0], o[r][1]);
        p[1] = __floats2half2_rn(o[r][2], o[r][3]);
    }

    float a1v[4], a2v[4];
#pragma unroll
    for (int j = 0; j < 4; j++) { a1v[j] = a[lc + j]; a2v[j] = a[64 + lc + j]; }
#pragma unroll
    for (int r = 0; r < 2; r++) {
        float p1 = 0.f, p2 = 0.f;
#pragma unroll
        for (int j = 0; j < 4; j++) {
            p1 = fmaf(o[r][j], a1v[j], p1);
            p2 = fmaf(o[r][j], a2v[j], p2);
        }
#pragma unroll
        for (int os = 8; os; os >>= 1) {
            p1 += __shfl_xor_sync(0xffffffffu, p1, os);
            p2 += __shfl_xor_sync(0xffffffffu, p2, os);
        }
        int row = rowBase + r0 + r;
        if (cx == 0)  { g_s1a[row] = p1; g_s2a[row] = p2; }
        if (cx == 16) { g_s1b[row] = p1; g_s2b[row] = p2; }
    }

    if (blockIdx.x == 0 && t < 128) { g_bnsum[t] = 0.f; g_bnsq[t] = 0.f; }
}

// ============ shared helpers =================================================
__device__ __forceinline__ int build_nbr(const unsigned* __restrict__ bits,
                                         unsigned short* nbr, int* wsum,
                                         int t, int lane, int warp)
{
    int n = (t < NW) ? __popc(bits[t]) : 0;
    int sc = n;
#pragma unroll
    for (int o = 1; o < 32; o <<= 1) {
        int v = __shfl_up_sync(0xffffffffu, sc, o);
        if (lane >= o) sc += v;
    }
    if (lane == 31) wsum[warp] = sc;
    __syncthreads();
    int wbase = 0;
#pragma unroll
    for (int w = 0; w < 8; w++) if (w < warp) wbase += wsum[w];
    int base = wbase + sc - n;
    if (t < NW) {
        unsigned m = bits[t];
        int b = base;
        while (m) { int bit = __ffs(m) - 1; m &= m - 1; nbr[b++] = (unsigned short)(t * 32 + bit); }
    }
    int deg = 0;
#pragma unroll
    for (int w = 0; w < 8; w++) deg += wsum[w];
    __syncthreads();
    return deg;
}

// cold path: degree-0 row -> uniform softmax == column mean (P ~ 1e-9)
__device__ void colmean_fallback(int i, int t, const __half* __restrict__ Whh, int colOff)
{
    if (t < F) {
        float s = 0.f;
        for (int r = 0; r < NPROT; r++) s += __half2float(Whh[r * F + t]);
        g_hp[i * 128 + colOff + t] = s * (1.f / NPROT);
    }
}

// sparse softmax + aggregate, single-pass exp (no max shift; |e| is small
// enough that fp32 exp cannot overflow). Phase 1: cooperative sweep computes
// exp once per edge into smem. Phase 2: 32 edge slots x 8 lanes, one uint4
// (128B line) per edge, 4-deep unroll. Cross-slot reduction via shfl_xor,
// then 8-warp smem reduce.
__device__ __forceinline__ void attn_aggregate(
    int i, int t, int deg, const unsigned short* __restrict__ nbr,
    float* ecache, float4* redw /*[8*16]*/, float* dsh, float s1i,
    const float* __restrict__ s2, const __half* __restrict__ Whh, int colOff)
{
    for (int k = t; k < deg; k += 256) {
        float e = s1i + s2[nbr[k]];
        e = (e > 0.f) ? e : ALPHA * e;
        ecache[k] = __expf(e);
    }
    __syncthreads();

    int slot = t >> 3, ll = t & 7;                 // 32 slots x 8 lanes
    int lane = t & 31, warp = t >> 5;
    const uint4* __restrict__ Whq = (const uint4*)Whh;   // 8 uint4 per row

    float4 aL = {0.f, 0.f, 0.f, 0.f}, aH = {0.f, 0.f, 0.f, 0.f};
    float den = 0.f;
    int k = slot;
    for (; k + 96 < deg; k += 128) {
        int j0 = nbr[k], j1 = nbr[k + 32], j2 = nbr[k + 64], j3 = nbr[k + 96];
        uint4 u0 = Whq[j0 * 8 + ll];
        uint4 u1 = Whq[j1 * 8 + ll];
        uint4 u2 = Whq[j2 * 8 + ll];
        uint4 u3 = Whq[j3 * 8 + ll];
        float v0 = ecache[k], v1 = ecache[k + 32];
        float v2 = ecache[k + 64], v3 = ecache[k + 96];
        den += v0 + v1 + v2 + v3;
        {
            float2 p0 = __half22float2(*(const __half2*)&u0.x);
            float2 p1 = __half22float2(*(const __half2*)&u0.y);
            float2 p2 = __half22float2(*(const __half2*)&u0.z);
            float2 p3 = __half22float2(*(const __half2*)&u0.w);
            aL.x = fmaf(v0, p0.x, aL.x); aL.y = fmaf(v0, p0.y, aL.y);
            aL.z = fmaf(v0, p1.x, aL.z); aL.w = fmaf(v0, p1.y, aL.w);
            aH.x = fmaf(v0, p2.x, aH.x); aH.y = fmaf(v0, p2.y, aH.y);
            aH.z = fmaf(v0, p3.x, aH.z); aH.w = fmaf(v0, p3.y, aH.w);
        }
        {
            float2 p0 = __half22float2(*(const __half2*)&u1.x);
            float2 p1 = __half22float2(*(const __half2*)&u1.y);
            float2 p2 = __half22float2(*(const __half2*)&u1.z);
            float2 p3 = __half22float2(*(const __half2*)&u1.w);
            aL.x = fmaf(v1, p0.x, aL.x); aL.y = fmaf(v1, p0.y, aL.y);
            aL.z = fmaf(v1, p1.x, aL.z); aL.w = fmaf(v1, p1.y, aL.w);
            aH.x = fmaf(v1, p2.x, aH.x); aH.y = fmaf(v1, p2.y, aH.y);
            aH.z = fmaf(v1, p3.x, aH.z); aH.w = fmaf(v1, p3.y, aH.w);
        }
        {
            float2 p0 = __half22float2(*(const __half2*)&u2.x);
            float2 p1 = __half22float2(*(const __half2*)&u2.y);
            float2 p2 = __half22float2(*(const __half2*)&u2.z);
            float2 p3 = __half22float2(*(const __half2*)&u2.w);
            aL.x = fmaf(v2, p0.x, aL.x); aL.y = fmaf(v2, p0.y, aL.y);
            aL.z = fmaf(v2, p1.x, aL.z); aL.w = fmaf(v2, p1.y, aL.w);
            aH.x = fmaf(v2, p2.x, aH.x); aH.y = fmaf(v2, p2.y, aH.y);
            aH.z = fmaf(v2, p3.x, aH.z); aH.w = fmaf(v2, p3.y, aH.w);
        }
        {
            float2 p0 = __half22float2(*(const __half2*)&u3.x);
            float2 p1 = __half22float2(*(const __half2*)&u3.y);
            float2 p2 = __half22float2(*(const __half2*)&u3.z);
            float2 p3 = __half22float2(*(const __half2*)&u3.w);
            aL.x = fmaf(v3, p0.x, aL.x); aL.y = fmaf(v3, p0.y, aL.y);
            aL.z = fmaf(v3, p1.x, aL.z); aL.w = fmaf(v3, p1.y, aL.w);
            aH.x = fmaf(v3, p2.x, aH.x); aH.y = fmaf(v3, p2.y, aH.y);
            aH.z = fmaf(v3, p3.x, aH.z); aH.w = fmaf(v3, p3.y, aH.w);
        }
    }
    for (; k < deg; k += 32) {
        int j = nbr[k];
        uint4 u = Whq[j * 8 + ll];
        float v = ecache[k];
        den += v;
        float2 p0 = __half22float2(*(const __half2*)&u.x);
        float2 p1 = __half22float2(*(const __half2*)&u.y);
        float2 p2 = __half22float2(*(const __half2*)&u.z);
        float2 p3 = __half22float2(*(const __half2*)&u.w);
        aL.x = fmaf(v, p0.x, aL.x); aL.y = fmaf(v, p0.y, aL.y);
        aL.z = fmaf(v, p1.x, aL.z); aL.w = fmaf(v, p1.y, aL.w);
        aH.x = fmaf(v, p2.x, aH.x); aH.y = fmaf(v, p2.y, aH.y);
        aH.z = fmaf(v, p3.x, aH.z); aH.w = fmaf(v, p3.y, aH.w);
    }

    // combine the 4 slots within each warp (same ll, lanes differ by bits 3-4)
#pragma unroll
    for (int off = 16; off >= 8; off >>= 1) {
        aL.x += __shfl_xor_sync(0xffffffffu, aL.x, off);
        aL.y += __shfl_xor_sync(0xffffffffu, aL.y, off);
        aL.z += __shfl_xor_sync(0xffffffffu, aL.z, off);
        aL.w += __shfl_xor_sync(0xffffffffu, aL.w, off);
        aH.x += __shfl_xor_sync(0xffffffffu, aH.x, off);
        aH.y += __shfl_xor_sync(0xffffffffu, aH.y, off);
        aH.z += __shfl_xor_sync(0xffffffffu, aH.z, off);
        aH.w += __shfl_xor_sync(0xffffffffu, aH.w, off);
        den  += __shfl_xor_sync(0xffffffffu, den,  off);
    }
    if (lane < 8) {
        redw[warp * 16 + ll * 2]     = aL;
        redw[warp * 16 + ll * 2 + 1] = aH;
        if (lane == 0) dsh[warp] = den;
    }
    __syncthreads();
    if (t < 16) {                                  // t = ll*2 + p
        float4 s = {0.f, 0.f, 0.f, 0.f};
        float dtot = 0.f;
#pragma unroll
        for (int w = 0; w < 8; w++) {
            float4 v = redw[w * 16 + t];
            s.x += v.x; s.y += v.y; s.z += v.z; s.w += v.w;
            dtot += dsh[w];
        }
        float inv = 1.f / dtot;
        float4 o = make_float4(s.x * inv, s.y * inv, s.z * inv, s.w * inv);
        *(float4*)&g_hp[i * 128 + colOff + t * 4] = o;
    }
    __syncthreads();                               // protect smem reuse
}

// ============ kernel 3: PERSISTENT fused hop-1 + adj^2 + hop-2 attention =====
__global__ __launch_bounds__(256) void k_attn()
{
    __shared__ unsigned       sbits[NW];
    __shared__ __align__(16) unsigned bits2[NW];
    __shared__ unsigned short nbr[NPROT];
    __shared__ float          ecache[NPROT];
    __shared__ __align__(16) float4 redw[8 * 16];
    __shared__ float          dsh[8];
    __shared__ int            wsum[8];

    int t = threadIdx.x;
    int lane = t & 31, warp = t >> 5;

    for (int i = blockIdx.x; i < NPROT; i += gridDim.x) {
        if (t < NW) { sbits[t] = g_bits1[i * NW + t]; bits2[t] = 0u; }
        __syncthreads();

        int deg1 = build_nbr(sbits, nbr, wsum, t, lane, warp);

        // bits2 row i = OR of neighbor rows. uint4 loads: 32 uint4-words,
        // 8 neighbor-stride groups, 4 smem atomicOr per thread.
        {
            int q = t & 31, sub = t >> 5;
            unsigned a0 = 0u, a1 = 0u, a2 = 0u, a3 = 0u;
            for (int k = sub; k < deg1; k += 8) {
                uint4 u = *(const uint4*)&g_bits1[(int)nbr[k] * NW + q * 4];
                a0 |= u.x; a1 |= u.y; a2 |= u.z; a3 |= u.w;
            }
            if (a0) atomicOr(&bits2[q * 4],     a0);
            if (a1) atomicOr(&bits2[q * 4 + 1], a1);
            if (a2) atomicOr(&bits2[q * 4 + 2], a2);
            if (a3) atomicOr(&bits2[q * 4 + 3], a3);
        }

        // hop 1 (uses nbr1; OR loop above doesn't modify nbr)
        if (deg1 == 0) colmean_fallback(i, t, g_Wh1h, 0);
        else attn_aggregate(i, t, deg1, nbr, ecache, redw, dsh, g_s1a[i], g_s2a, g_Wh1h, 0);

        __syncthreads();                                // OR atomics + hop1 done
        if (t == 0) bits2[i >> 5] &= ~(1u << (i & 31)); // zero diagonal of adj2
        __syncthreads();

        int deg2 = build_nbr(bits2, nbr, wsum, t, lane, warp);
        if (deg2 == 0) colmean_fallback(i, t, g_Wh2h, 64);
        else attn_aggregate(i, t, deg2, nbr, ecache, redw, dsh, g_s1b[i], g_s2b, g_Wh2h, 64);

        __syncthreads();                                // smem reuse across rows
    }
}

// ============ kernel 4: BN stats (128 blocks x 32 rows, float4) ==============
__global__ __launch_bounds__(256) void k_bnstats()
{
    int b = blockIdx.x, t = threadIdx.x;
    int c4 = t & 31, rg = t >> 5;                  // 8 row-groups
    const float4* hp4 = (const float4*)g_hp;
    float4 s = {0.f, 0.f, 0.f, 0.f}, q = {0.f, 0.f, 0.f, 0.f};
#pragma unroll
    for (int i2 = 0; i2 < 4; i2++) {
        float4 v = hp4[(b * 32 + rg + 8 * i2) * 32 + c4];
        s.x += v.x; s.y += v.y; s.z += v.z; s.w += v.w;
        q.x = fmaf(v.x, v.x, q.x); q.y = fmaf(v.y, v.y, q.y);
        q.z = fmaf(v.z, v.z, q.z); q.w = fmaf(v.w, v.w, q.w);
    }
    __shared__ float4 ss[256], qq[256];
    ss[t] = s; qq[t] = q;
    __syncthreads();
#pragma unroll
    for (int st = 4; st > 0; st >>= 1) {           // reduce over row-groups
        if (rg < st) {
            float4 a = ss[t], b2 = ss[t + st * 32];
            a.x += b2.x; a.y += b2.y; a.z += b2.z; a.w += b2.w; ss[t] = a;
            float4 c = qq[t], d = qq[t + st * 32];
            c.x += d.x; c.y += d.y; c.z += d.z; c.w += d.w; qq[t] = c;
        }
        __syncthreads();
    }
    if (t < 32) {
        int c = t * 4;
        float4 a = ss[t], qv = qq[t];
        atomicAdd(&g_bnsum[c],     a.x);  atomicAdd(&g_bnsum[c + 1], a.y);
        atomicAdd(&g_bnsum[c + 2], a.z);  atomicAdd(&g_bnsum[c + 3], a.w);
        atomicAdd(&g_bnsq[c],      qv.x); atomicAdd(&g_bnsq[c + 1],  qv.y);
        atomicAdd(&g_bnsq[c + 2],  qv.z); atomicAdd(&g_bnsq[c + 3],  qv.w);
    }
}

// ============ kernel 5: BN apply + leakyrelu (scale/shift derived in-block) ==
__global__ __launch_bounds__(256) void k_bnapply(const float* __restrict__ gamma,
                                                 const float* __restrict__ beta,
                                                 float* __restrict__ out)
{
    __shared__ float sc[128], sh[128];
    int t = threadIdx.x;
    if (t < 128) {
        float mean = g_bnsum[t] * (1.f / NPROT);
        float var  = g_bnsq[t] * (1.f / NPROT) - mean * mean;
        float s = gamma[t] * rsqrtf(var + 1e-5f);
        sc[t] = s;
        sh[t] = beta[t] - mean * s;
    }
    __syncthreads();
    int idx = blockIdx.x * 256 + t;                // NPROT*128/4 float4s
    int c = (idx & 31) * 4;
    float4 v = ((const float4*)g_hp)[idx];
    float4 o;
    o.x = fmaf(v.x, sc[c],     sh[c]);     o.x = (o.x > 0.f) ? o.x : ALPHA * o.x;
    o.y = fmaf(v.y, sc[c + 1], sh[c + 1]); o.y = (o.y > 0.f) ? o.y : ALPHA * o.y;
    o.z = fmaf(v.z, sc[c + 2], sh[c + 2]); o.z = (o.z > 0.f) ? o.z : ALPHA * o.z;
    o.w = fmaf(v.w, sc[c + 3], sh[c + 3]); o.w = (o.w > 0.f) ? o.w : ALPHA * o.w;
    ((float4*)out)[idx] = o;
}

// ============ launch ==========================================================
extern "C" void kernel_launch(void* const* d_in, const int* in_sizes, int n_in,
                              void* d_out, int out_size)
{
    const float* h     = (const float*)d_in[0];
    const float* adj   = (const float*)d_in[1];
    const float* W1    = (const float*)d_in[2];
    const float* W2    = (const float*)d_in[3];
    const float* a     = (const float*)d_in[4];
    const float* gamma = (const float*)d_in[5];
    const float* beta  = (const float*)d_in[6];
    float* out = (float*)d_out;

    k_pack    <<<NPROT, 256>>>(adj);
    k_wh      <<<NPROT / 16, 256>>>(h, W1, W2, a);
    k_attn    <<<ATTN_GRID, 256>>>();
    k_bnstats <<<NPROT / 32, 256>>>();
    k_bnapply <<<(NPROT * 128 / 4) / 256, 256>>>(gamma, beta, out);
}

// round 17
// speedup vs baseline: 1.1004x; 1.1004x over previous
#include <cuda_runtime.h>
#include <cuda_fp16.h>
#include <stdint.h>

#define NPROT 4096
#define IN_F  512
#define HALF  256
#define F     64
#define NW    128
#define ALPHA 0.2f
#define WH_BLOCKS (NPROT / 16)     // 256

typedef unsigned long long ull;

// ---------------- scratch (device globals; no allocation allowed) ----------
__device__ __align__(16) __half g_Wh1h[NPROT * F];
__device__ __align__(16) __half g_Wh2h[NPROT * F];
__device__ float    g_s1a[NPROT], g_s2a[NPROT];   // hop1 row/col scores
__device__ float    g_s1b[NPROT], g_s2b[NPROT];   // hop2
__device__ __align__(16) unsigned g_bits1[NPROT * NW];
__device__ float    g_hp[NPROT * 2 * F];
__device__ float    g_bnsum[2 * F], g_bnsq[2 * F];

// ---------------- packed fp32x2 helpers (sm_103a FFMA2 path) ----------------
__device__ __forceinline__ ull pack2(float lo, float hi) {
    ull r; asm("mov.b64 %0, {%1, %2};" : "=l"(r) : "f"(lo), "f"(hi)); return r;
}
__device__ __forceinline__ void unpack2(ull v, float& lo, float& hi) {
    asm("mov.b64 {%0, %1}, %2;" : "=f"(lo), "=f"(hi) : "l"(v));
}
__device__ __forceinline__ void ffma2(ull& acc, ull a, ull b) {
    asm("fma.rn.f32x2 %0, %1, %2, %0;" : "+l"(acc) : "l"(a), "l"(b));
}

// ============ kernel 1: FUSED front-end =====================================
// blocks [0, 256): Wh = h @ blockdiag(W1,W2) GEMM + score vectors (compute)
// blocks [256, 4352): bitpack one adj row each (pure DRAM stream)
// The two roles overlap on-chip: pack saturates DRAM while wh uses the idle
// FMA/issue slots.
__global__ __launch_bounds__(256) void k_prep(const float* __restrict__ h,
                                              const float* __restrict__ W1,
                                              const float* __restrict__ W2,
                                              const float* __restrict__ a,
                                              const float* __restrict__ adj)
{
    int t = threadIdx.x;

    if (blockIdx.x >= WH_BLOCKS) {
        // ---- pack role ----
        int i = blockIdx.x - WH_BLOCKS;
        int lane = t & 31, warp = t >> 5;
        const float* arow = adj + (size_t)i * NPROT;
#pragma unroll
        for (int w = 0; w < 16; w++) {
            unsigned m = __ballot_sync(0xffffffffu, arow[w * 256 + t] > 0.f);
            if (lane == 0) g_bits1[i * NW + w * 8 + warp] = m;
        }
        return;
    }

    // ---- wh role ----
    __shared__ float hsT[2][16][16];                 // [half][k][row]
    __shared__ __align__(16) float Ws[16][128];      // [k][col]

    int rowBase = blockIdx.x * 16;
    int cx = t & 31, ry = t >> 5;
    int half = (cx >= 16);
    int lc = (cx & 15) * 4;
    int r0 = ry * 2;

    ull acc[2][2] = {};

    int lhalf = t >> 7, lt63 = t & 63;
    int lrow = lt63 >> 2, lk4 = (lt63 & 3) * 4;
    int wkk = t >> 4, wc8 = (t & 15) * 8;

    for (int k0 = 0; k0 < HALF; k0 += 16) {
        if ((t & 127) < 64) {
            float4 hv = *(const float4*)&h[(rowBase + lrow) * IN_F + lhalf * HALF + k0 + lk4];
            hsT[lhalf][lk4 + 0][lrow] = hv.x;
            hsT[lhalf][lk4 + 1][lrow] = hv.y;
            hsT[lhalf][lk4 + 2][lrow] = hv.z;
            hsT[lhalf][lk4 + 3][lrow] = hv.w;
        }
        const float* Wsrc = (wc8 < 64) ? &W1[(k0 + wkk) * F + wc8]
                                       : &W2[(k0 + wkk) * F + (wc8 - 64)];
        *(float4*)&Ws[wkk][wc8]     = *(const float4*)Wsrc;
        *(float4*)&Ws[wkk][wc8 + 4] = *(const float4*)(Wsrc + 4);
        __syncthreads();
#pragma unroll
        for (int kk = 0; kk < 16; kk++) {
            float a0 = hsT[half][kk][r0];
            float a1 = hsT[half][kk][r0 + 1];
            ull A0 = pack2(a0, a0), A1 = pack2(a1, a1);
            ulonglong2 bb = *(const ulonglong2*)&Ws[kk][cx * 4];
            ffma2(acc[0][0], A0, bb.x); ffma2(acc[0][1], A0, bb.y);
            ffma2(acc[1][0], A1, bb.x); ffma2(acc[1][1], A1, bb.y);
        }
        __syncthreads();
    }

    float o[2][4];
    unpack2(acc[0][0], o[0][0], o[0][1]); unpack2(acc[0][1], o[0][2], o[0][3]);
    unpack2(acc[1][0], o[1][0], o[1][1]); unpack2(acc[1][1], o[1][2], o[1][3]);

    __half* dsth = half ? g_Wh2h : g_Wh1h;
#pragma unroll
    for (int r = 0; r < 2; r++) {
        __half2* p = (__half2*)&dsth[(rowBase + r0 + r) * F + lc];
        p[0] = __floats2half2_rn(o[r][0], o[r][1]);
        p[1] = __floats2half2_rn(o[r][2], o[r][3]);
    }

    float a1v[4], a2v[4];
#pragma unroll
    for (int j = 0; j < 4; j++) { a1v[j] = a[lc + j]; a2v[j] = a[64 + lc + j]; }
#pragma unroll
    for (int r = 0; r < 2; r++) {
        float p1 = 0.f, p2 = 0.f;
#pragma unroll
        for (int j = 0; j < 4; j++) {
            p1 = fmaf(o[r][j], a1v[j], p1);
            p2 = fmaf(o[r][j], a2v[j], p2);
        }
#pragma unroll
        for (int os = 8; os; os >>= 1) {
            p1 += __shfl_xor_sync(0xffffffffu, p1, os);
            p2 += __shfl_xor_sync(0xffffffffu, p2, os);
        }
        int row = rowBase + r0 + r;
        if (cx == 0)  { g_s1a[row] = p1; g_s2a[row] = p2; }
        if (cx == 16) { g_s1b[row] = p1; g_s2b[row] = p2; }
    }

    if (blockIdx.x == 0 && t < 128) { g_bnsum[t] = 0.f; g_bnsq[t] = 0.f; }
}

// ============ shared helpers =================================================
__device__ __forceinline__ int build_nbr(const unsigned* __restrict__ bits,
                                         unsigned short* nbr, int* wsum,
                                         int t, int lane, int warp)
{
    int n = (t < NW) ? __popc(bits[t]) : 0;
    int sc = n;
#pragma unroll
    for (int o = 1; o < 32; o <<= 1) {
        int v = __shfl_up_sync(0xffffffffu, sc, o);
        if (lane >= o) sc += v;
    }
    if (lane == 31) wsum[warp] = sc;
    __syncthreads();
    int wbase = 0;
#pragma unroll
    for (int w = 0; w < 8; w++) if (w < warp) wbase += wsum[w];
    int base = wbase + sc - n;
    if (t < NW) {
        unsigned m = bits[t];
        int b = base;
        while (m) { int bit = __ffs(m) - 1; m &= m - 1; nbr[b++] = (unsigned short)(t * 32 + bit); }
    }
    int deg = 0;
#pragma unroll
    for (int w = 0; w < 8; w++) deg += wsum[w];
    __syncthreads();
    return deg;
}

// cold path: degree-0 row -> uniform softmax == column mean (P ~ 1e-9)
__device__ void colmean_fallback(int i, int t, const __half* __restrict__ Whh, int colOff)
{
    if (t < F) {
        float s = 0.f;
        for (int r = 0; r < NPROT; r++) s += __half2float(Whh[r * F + t]);
        g_hp[i * 128 + colOff + t] = s * (1.f / NPROT);
    }
}

// sparse softmax + aggregate, single-pass exp (no max shift; |e| is small
// enough that fp32 exp cannot overflow). Phase 1: cooperative sweep computes
// exp once per edge into smem. Phase 2: 32 edge slots x 8 lanes, one uint4
// (128B line) per edge, 4-deep unroll. Cross-slot reduction via shfl_xor,
// then 8-warp smem reduce.
__device__ __forceinline__ void attn_aggregate(
    int i, int t, int deg, const unsigned short* __restrict__ nbr,
    float* ecache, float4* redw /*[8*16]*/, float* dsh, float s1i,
    const float* __restrict__ s2, const __half* __restrict__ Whh, int colOff)
{
    for (int k = t; k < deg; k += 256) {
        float e = s1i + s2[nbr[k]];
        e = (e > 0.f) ? e : ALPHA * e;
        ecache[k] = __expf(e);
    }
    __syncthreads();

    int slot = t >> 3, ll = t & 7;                 // 32 slots x 8 lanes
    int lane = t & 31, warp = t >> 5;
    const uint4* __restrict__ Whq = (const uint4*)Whh;   // 8 uint4 per row

    float4 aL = {0.f, 0.f, 0.f, 0.f}, aH = {0.f, 0.f, 0.f, 0.f};
    float den = 0.f;
    int k = slot;
    for (; k + 96 < deg; k += 128) {
        int j0 = nbr[k], j1 = nbr[k + 32], j2 = nbr[k + 64], j3 = nbr[k + 96];
        uint4 u0 = Whq[j0 * 8 + ll];
        uint4 u1 = Whq[j1 * 8 + ll];
        uint4 u2 = Whq[j2 * 8 + ll];
        uint4 u3 = Whq[j3 * 8 + ll];
        float v0 = ecache[k], v1 = ecache[k + 32];
        float v2 = ecache[k + 64], v3 = ecache[k + 96];
        den += v0 + v1 + v2 + v3;
        {
            float2 p0 = __half22float2(*(const __half2*)&u0.x);
            float2 p1 = __half22float2(*(const __half2*)&u0.y);
            float2 p2 = __half22float2(*(const __half2*)&u0.z);
            float2 p3 = __half22float2(*(const __half2*)&u0.w);
            aL.x = fmaf(v0, p0.x, aL.x); aL.y = fmaf(v0, p0.y, aL.y);
            aL.z = fmaf(v0, p1.x, aL.z); aL.w = fmaf(v0, p1.y, aL.w);
            aH.x = fmaf(v0, p2.x, aH.x); aH.y = fmaf(v0, p2.y, aH.y);
            aH.z = fmaf(v0, p3.x, aH.z); aH.w = fmaf(v0, p3.y, aH.w);
        }
        {
            float2 p0 = __half22float2(*(const __half2*)&u1.x);
            float2 p1 = __half22float2(*(const __half2*)&u1.y);
            float2 p2 = __half22float2(*(const __half2*)&u1.z);
            float2 p3 = __half22float2(*(const __half2*)&u1.w);
            aL.x = fmaf(v1, p0.x, aL.x); aL.y = fmaf(v1, p0.y, aL.y);
            aL.z = fmaf(v1, p1.x, aL.z); aL.w = fmaf(v1, p1.y, aL.w);
            aH.x = fmaf(v1, p2.x, aH.x); aH.y = fmaf(v1, p2.y, aH.y);
            aH.z = fmaf(v1, p3.x, aH.z); aH.w = fmaf(v1, p3.y, aH.w);
        }
        {
            float2 p0 = __half22float2(*(const __half2*)&u2.x);
            float2 p1 = __half22float2(*(const __half2*)&u2.y);
            float2 p2 = __half22float2(*(const __half2*)&u2.z);
            float2 p3 = __half22float2(*(const __half2*)&u2.w);
            aL.x = fmaf(v2, p0.x, aL.x); aL.y = fmaf(v2, p0.y, aL.y);
            aL.z = fmaf(v2, p1.x, aL.z); aL.w = fmaf(v2, p1.y, aL.w);
            aH.x = fmaf(v2, p2.x, aH.x); aH.y = fmaf(v2, p2.y, aH.y);
            aH.z = fmaf(v2, p3.x, aH.z); aH.w = fmaf(v2, p3.y, aH.w);
        }
        {
            float2 p0 = __half22float2(*(const __half2*)&u3.x);
            float2 p1 = __half22float2(*(const __half2*)&u3.y);
            float2 p2 = __half22float2(*(const __half2*)&u3.z);
            float2 p3 = __half22float2(*(const __half2*)&u3.w);
            aL.x = fmaf(v3, p0.x, aL.x); aL.y = fmaf(v3, p0.y, aL.y);
            aL.z = fmaf(v3, p1.x, aL.z); aL.w = fmaf(v3, p1.y, aL.w);
            aH.x = fmaf(v3, p2.x, aH.x); aH.y = fmaf(v3, p2.y, aH.y);
            aH.z = fmaf(v3, p3.x, aH.z); aH.w = fmaf(v3, p3.y, aH.w);
        }
    }
    for (; k < deg; k += 32) {
        int j = nbr[k];
        uint4 u = Whq[j * 8 + ll];
        float v = ecache[k];
        den += v;
        float2 p0 = __half22float2(*(const __half2*)&u.x);
        float2 p1 = __half22float2(*(const __half2*)&u.y);
        float2 p2 = __half22float2(*(const __half2*)&u.z);
        float2 p3 = __half22float2(*(const __half2*)&u.w);
        aL.x = fmaf(v, p0.x, aL.x); aL.y = fmaf(v, p0.y, aL.y);
        aL.z = fmaf(v, p1.x, aL.z); aL.w = fmaf(v, p1.y, aL.w);
        aH.x = fmaf(v, p2.x, aH.x); aH.y = fmaf(v, p2.y, aH.y);
        aH.z = fmaf(v, p3.x, aH.z); aH.w = fmaf(v, p3.y, aH.w);
    }

    // combine the 4 slots within each warp (same ll, lanes differ by bits 3-4)
#pragma unroll
    for (int off = 16; off >= 8; off >>= 1) {
        aL.x += __shfl_xor_sync(0xffffffffu, aL.x, off);
        aL.y += __shfl_xor_sync(0xffffffffu, aL.y, off);
        aL.z += __shfl_xor_sync(0xffffffffu, aL.z, off);
        aL.w += __shfl_xor_sync(0xffffffffu, aL.w, off);
        aH.x += __shfl_xor_sync(0xffffffffu, aH.x, off);
        aH.y += __shfl_xor_sync(0xffffffffu, aH.y, off);
        aH.z += __shfl_xor_sync(0xffffffffu, aH.z, off);
        aH.w += __shfl_xor_sync(0xffffffffu, aH.w, off);
        den  += __shfl_xor_sync(0xffffffffu, den,  off);
    }
    if (lane < 8) {
        redw[warp * 16 + ll * 2]     = aL;
        redw[warp * 16 + ll * 2 + 1] = aH;
        if (lane == 0) dsh[warp] = den;
    }
    __syncthreads();
    if (t < 16) {                                  // t = ll*2 + p
        float4 s = {0.f, 0.f, 0.f, 0.f};
        float dtot = 0.f;
#pragma unroll
        for (int w = 0; w < 8; w++) {
            float4 v = redw[w * 16 + t];
            s.x += v.x; s.y += v.y; s.z += v.z; s.w += v.w;
            dtot += dsh[w];
        }
        float inv = 1.f / dtot;
        float4 o = make_float4(s.x * inv, s.y * inv, s.z * inv, s.w * inv);
        *(float4*)&g_hp[i * 128 + colOff + t * 4] = o;
    }
    __syncthreads();                               // protect smem reuse
}

// ============ kernel 2: fused hop-1 + adj^2 + hop-2 attention (4096 blocks) ==
__global__ __launch_bounds__(256) void k_attn()
{
    __shared__ unsigned       sbits[NW];
    __shared__ unsigned       bits2[NW];
    __shared__ unsigned short nbr[NPROT];
    __shared__ float          ecache[NPROT];
    __shared__ __align__(16) float4 redw[8 * 16];
    __shared__ float          dsh[8];
    __shared__ int            wsum[8];

    int i = blockIdx.x, t = threadIdx.x;
    int lane = t & 31, warp = t >> 5;

    if (t < NW) { sbits[t] = g_bits1[i * NW + t]; bits2[t] = 0u; }
    __syncthreads();

    int deg1 = build_nbr(sbits, nbr, wsum, t, lane, warp);

    // bits2 row i = OR of neighbor rows (2 threads per word)
    {
        int word = t & 127, hh = t >> 7;
        unsigned acc = 0u;
        for (int k = hh; k < deg1; k += 2)
            acc |= g_bits1[(int)nbr[k] * NW + word];
        if (acc) atomicOr(&bits2[word], acc);
    }

    // hop 1 (uses nbr1; OR loop above doesn't modify nbr)
    if (deg1 == 0) colmean_fallback(i, t, g_Wh1h, 0);
    else attn_aggregate(i, t, deg1, nbr, ecache, redw, dsh, g_s1a[i], g_s2a, g_Wh1h, 0);

    __syncthreads();                                // OR atomics + hop1 done
    if (t == 0) bits2[i >> 5] &= ~(1u << (i & 31)); // zero diagonal of adj2
    __syncthreads();

    int deg2 = build_nbr(bits2, nbr, wsum, t, lane, warp);
    if (deg2 == 0) colmean_fallback(i, t, g_Wh2h, 64);
    else attn_aggregate(i, t, deg2, nbr, ecache, redw, dsh, g_s1b[i], g_s2b, g_Wh2h, 64);
}

// ============ kernel 3: BN stats (128 blocks x 32 rows, float4) ==============
__global__ __launch_bounds__(256) void k_bnstats()
{
    int b = blockIdx.x, t = threadIdx.x;
    int c4 = t & 31, rg = t >> 5;                  // 8 row-groups
    const float4* hp4 = (const float4*)g_hp;
    float4 s = {0.f, 0.f, 0.f, 0.f}, q = {0.f, 0.f, 0.f, 0.f};
#pragma unroll
    for (int i2 = 0; i2 < 4; i2++) {
        float4 v = hp4[(b * 32 + rg + 8 * i2) * 32 + c4];
        s.x += v.x; s.y += v.y; s.z += v.z; s.w += v.w;
        q.x = fmaf(v.x, v.x, q.x); q.y = fmaf(v.y, v.y, q.y);
        q.z = fmaf(v.z, v.z, q.z); q.w = fmaf(v.w, v.w, q.w);
    }
    __shared__ float4 ss[256], qq[256];
    ss[t] = s; qq[t] = q;
    __syncthreads();
#pragma unroll
    for (int st = 4; st > 0; st >>= 1) {           // reduce over row-groups
        if (rg < st) {
            float4 a = ss[t], b2 = ss[t + st * 32];
            a.x += b2.x; a.y += b2.y; a.z += b2.z; a.w += b2.w; ss[t] = a;
            float4 c = qq[t], d = qq[t + st * 32];
            c.x += d.x; c.y += d.y; c.z += d.z; c.w += d.w; qq[t] = c;
        }
        __syncthreads();
    }
    if (t < 32) {
        int c = t * 4;
        float4 a = ss[t], qv = qq[t];
        atomicAdd(&g_bnsum[c],     a.x);  atomicAdd(&g_bnsum[c + 1], a.y);
        atomicAdd(&g_bnsum[c + 2], a.z);  atomicAdd(&g_bnsum[c + 3], a.w);
        atomicAdd(&g_bnsq[c],      qv.x); atomicAdd(&g_bnsq[c + 1],  qv.y);
        atomicAdd(&g_bnsq[c + 2],  qv.z); atomicAdd(&g_bnsq[c + 3],  qv.w);
    }
}

// ============ kernel 4: BN apply + leakyrelu (scale/shift derived in-block) ==
__global__ __launch_bounds__(256) void k_bnapply(const float* __restrict__ gamma,
                                                 const float* __restrict__ beta,
                                                 float* __restrict__ out)
{
    __shared__ float sc[128], sh[128];
    int t = threadIdx.x;
    if (t < 128) {
        float mean = g_bnsum[t] * (1.f / NPROT);
        float var  = g_bnsq[t] * (1.f / NPROT) - mean * mean;
        float s = gamma[t] * rsqrtf(var + 1e-5f);
        sc[t] = s;
        sh[t] = beta[t] - mean * s;
    }
    __syncthreads();
    int idx = blockIdx.x * 256 + t;                // NPROT*128/4 float4s
    int c = (idx & 31) * 4;
    float4 v = ((const float4*)g_hp)[idx];
    float4 o;
    o.x = fmaf(v.x, sc[c],     sh[c]);     o.x = (o.x > 0.f) ? o.x : ALPHA * o.x;
    o.y = fmaf(v.y, sc[c + 1], sh[c + 1]); o.y = (o.y > 0.f) ? o.y : ALPHA * o.y;
    o.z = fmaf(v.z, sc[c + 2], sh[c + 2]); o.z = (o.z > 0.f) ? o.z : ALPHA * o.z;
    o.w = fmaf(v.w, sc[c + 3], sh[c + 3]); o.w = (o.w > 0.f) ? o.w : ALPHA * o.w;
    ((float4*)out)[idx] = o;
}

// ============ launch ==========================================================
extern "C" void kernel_launch(void* const* d_in, const int* in_sizes, int n_in,
                              void* d_out, int out_size)
{
    const float* h     = (const float*)d_in[0];
    const float* adj   = (const float*)d_in[1];
    const float* W1    = (const float*)d_in[2];
    const float* W2    = (const float*)d_in[3];
    const float* a     = (const float*)d_in[4];
    const float* gamma = (const float*)d_in[5];
    const float* beta  = (const float*)d_in[6];
    float* out = (float*)d_out;

    k_prep    <<<WH_BLOCKS + NPROT, 256>>>(h, W1, W2, a, adj);
    k_attn    <<<NPROT, 256>>>();
    k_bnstats <<<NPROT / 32, 256>>>();
    k_bnapply <<<(NPROT * 128 / 4) / 256, 256>>>(gamma, beta, out);
}